// round 6
// baseline (speedup 1.0000x reference)
#include <cuda_runtime.h>
#include <cuda_bf16.h>
#include <stdint.h>

#define N_NODES 50000
#define N_EDGES 50000
#define IN_C 256
#define HID_C 128
#define OUT_C 64
#define MAX_NNZ 800000

// ---------------- scratch (no allocations allowed) ----------------
__device__ float g_h0[(size_t)N_NODES * HID_C];   // x @ W1
__device__ float g_m [(size_t)N_EDGES * HID_C];   // edge aggregation buffer (reused at C=64)
__device__ float g_h1[(size_t)N_NODES * OUT_C];   // f1 @ W2
__device__ float g_dinv[N_NODES];
__device__ float g_binv[N_EDGES];

// one contiguous block: [ecnt | ncnt | ecur | ncur] -> single memset
__device__ int g_cnt[4 * N_EDGES];
__device__ int g_eoff[N_EDGES + 1];
__device__ int g_noff[N_NODES + 1];
__device__ int g_eadj[MAX_NNZ];   // per edge-row: node indices
__device__ int g_nadj[MAX_NNZ];   // per node-row: edge indices

// ---------------- histogram ----------------
__global__ void hist_kernel(const int* __restrict__ node_idx,
                            const int* __restrict__ edge_idx,
                            int* __restrict__ ncnt, int* __restrict__ ecnt, int nnz) {
    int t = blockIdx.x * blockDim.x + threadIdx.x;
    if (t < nnz) {
        atomicAdd(&ncnt[node_idx[t]], 1);
        atomicAdd(&ecnt[edge_idx[t]], 1);
    }
}

// ---------------- exclusive scan over 50k ints + fused 1/count ----------------
__global__ void scan_kernel(const int* __restrict__ cntE, int* __restrict__ offE,
                            const int* __restrict__ cntN, int* __restrict__ offN,
                            float* __restrict__ binv, float* __restrict__ dinv, int n) {
    const int* cnt = (blockIdx.x == 0) ? cntE : cntN;
    int* off       = (blockIdx.x == 0) ? offE : offN;
    float* inv     = (blockIdx.x == 0) ? binv : dinv;
    __shared__ int sh[1024];
    int tid = threadIdx.x;
    int chunk = (n + 1023) / 1024;
    int start = tid * chunk;
    int end = min(start + chunk, n);
    int s = 0;
    for (int i = start; i < end; i++) {
        int c = cnt[i];
        s += c;
        inv[i] = (c > 0) ? (1.0f / (float)c) : 0.0f;
    }
    sh[tid] = s;
    __syncthreads();
    for (int d = 1; d < 1024; d <<= 1) {
        int v = (tid >= d) ? sh[tid - d] : 0;
        __syncthreads();
        sh[tid] += v;
        __syncthreads();
    }
    int run = (tid == 0) ? 0 : sh[tid - 1];
    for (int i = start; i < end; i++) {
        off[i] = run;
        run += cnt[i];
    }
    if (tid == 1023) off[n] = sh[1023];
}

// ---------------- CSR fill ----------------
__global__ void fill_kernel(const int* __restrict__ node_idx, const int* __restrict__ edge_idx,
                            const int* __restrict__ eoff, const int* __restrict__ noff,
                            int* __restrict__ ecur, int* __restrict__ ncur,
                            int* __restrict__ eadj, int* __restrict__ nadj, int nnz) {
    int t = blockIdx.x * blockDim.x + threadIdx.x;
    if (t < nnz) {
        int nd = node_idx[t];
        int eg = edge_idx[t];
        int p = atomicAdd(&ecur[eg], 1);
        eadj[eoff[eg] + p] = nd;
        int q = atomicAdd(&ncur[nd], 1);
        nadj[noff[nd] + q] = eg;
    }
}

// ---------------- warp-per-row gather-reduce ----------------
template <int VEC, bool SRC_SCALE, bool FINAL>
__global__ void agg_kernel(const float* __restrict__ src, const int* __restrict__ adj,
                           const int* __restrict__ off, const float* __restrict__ sscale,
                           float* __restrict__ out, const float* __restrict__ rscale,
                           const float* __restrict__ bias, int rows) {
    int warp = (blockIdx.x * blockDim.x + threadIdx.x) >> 5;
    int lane = threadIdx.x & 31;
    if (warp >= rows) return;
    const int C = 32 * VEC;
    int s0 = off[warp];
    int s1 = off[warp + 1];

    float acc[VEC];
#pragma unroll
    for (int k = 0; k < VEC; k++) acc[k] = 0.0f;

    for (int j = s0; j < s1; j++) {
        int nb = adj[j];
        float sc = SRC_SCALE ? sscale[nb] : 1.0f;
        const float* p = src + (size_t)nb * C + lane * VEC;
        if (VEC == 4) {
            float4 v = *reinterpret_cast<const float4*>(p);
            acc[0] += v.x * sc; acc[1] += v.y * sc;
            acc[2] += v.z * sc; acc[3] += v.w * sc;
        } else {
            float2 v = *reinterpret_cast<const float2*>(p);
            acc[0] += v.x * sc; acc[1] += v.y * sc;
        }
    }

    float* q = out + (size_t)warp * C + lane * VEC;
    if (FINAL) {
        float rs = rscale[warp];
#pragma unroll
        for (int k = 0; k < VEC; k++)
            acc[k] = fmaxf(acc[k] * rs + bias[lane * VEC + k], 0.0f);
    }
    if (VEC == 4) {
        *reinterpret_cast<float4*>(q) = make_float4(acc[0], acc[1], acc[2], acc[3]);
    } else {
        *reinterpret_cast<float2*>(q) = make_float2(acc[0], acc[1]);
    }
}

// ---------------- proven 64x64x16 fp32 GEMM (gemm1) ----------------
__global__ void sgemm_kernel(const float* __restrict__ A, const float* __restrict__ B,
                             float* __restrict__ C, int M, int N, int K,
                             const float* __restrict__ bias) {
    const int BM = 64, BN = 64, BK = 16;
    __shared__ float As[BK][BM + 1];
    __shared__ float Bs[BK][BN];

    int tid = threadIdx.x;
    int tr = tid / 16;
    int tc = tid % 16;
    int rowBase = blockIdx.x * BM;
    int colBase = blockIdx.y * BN;

    float acc[4][4] = {};

    for (int k0 = 0; k0 < K; k0 += BK) {
#pragma unroll
        for (int i = 0; i < 4; i++) {
            int linear = tid + i * 256;
            int r = linear / BK;
            int c = linear % BK;
            int gr = rowBase + r;
            As[c][r] = (gr < M) ? A[(size_t)gr * K + k0 + c] : 0.0f;
        }
#pragma unroll
        for (int i = 0; i < 4; i++) {
            int linear = tid + i * 256;
            int r = linear / BN;
            int c = linear % BN;
            Bs[r][c] = B[(size_t)(k0 + r) * N + colBase + c];
        }
        __syncthreads();

#pragma unroll
        for (int kk = 0; kk < BK; kk++) {
            float a[4], b[4];
#pragma unroll
            for (int i = 0; i < 4; i++) a[i] = As[kk][tr * 4 + i];
#pragma unroll
            for (int j = 0; j < 4; j++) b[j] = Bs[kk][tc * 4 + j];
#pragma unroll
            for (int i = 0; i < 4; i++)
#pragma unroll
                for (int j = 0; j < 4; j++)
                    acc[i][j] += a[i] * b[j];
        }
        __syncthreads();
    }

#pragma unroll
    for (int i = 0; i < 4; i++) {
        int gr = rowBase + tr * 4 + i;
        if (gr >= M) continue;
#pragma unroll
        for (int j = 0; j < 4; j++) {
            int gc = colBase + tc * 4 + j;
            float v = acc[i][j];
            if (bias) v += bias[gc];
            C[(size_t)gr * N + gc] = v;
        }
    }
}

// ---------------- 128x64x16 TM8/TN4 GEMM (gemm2/3, N multiple of 64) ----------------
template <int BM, int BN, int BK, int TM, int TN>
__global__ void __launch_bounds__(256, 2)
gemm_tpl(const float* __restrict__ A, const float* __restrict__ B,
         float* __restrict__ C, int M, int K,
         const float* __restrict__ bias) {
    const int N = BN * gridDim.y;
    __shared__ float As[BK][BM + 4];
    __shared__ float Bs[BK][BN];

    int tid = threadIdx.x;
    const int TCN = BN / TN;
    int tr = tid / TCN;
    int tc = tid % TCN;
    int rowBase = blockIdx.x * BM;
    int colBase = blockIdx.y * BN;

    float acc[TM][TN];
#pragma unroll
    for (int i = 0; i < TM; i++)
#pragma unroll
        for (int j = 0; j < TN; j++) acc[i][j] = 0.0f;

    for (int k0 = 0; k0 < K; k0 += BK) {
#pragma unroll
        for (int i = tid * 4; i < BM * BK; i += 256 * 4) {
            int r = i / BK;
            int c = i % BK;
            int gr = rowBase + r;
            float4 v = make_float4(0.f, 0.f, 0.f, 0.f);
            if (gr < M)
                v = *reinterpret_cast<const float4*>(A + (size_t)gr * K + k0 + c);
            As[c + 0][r] = v.x;
            As[c + 1][r] = v.y;
            As[c + 2][r] = v.z;
            As[c + 3][r] = v.w;
        }
#pragma unroll
        for (int i = tid * 4; i < BK * BN; i += 256 * 4) {
            int r = i / BN;
            int c = i % BN;
            *reinterpret_cast<float4*>(&Bs[r][c]) =
                *reinterpret_cast<const float4*>(B + (size_t)(k0 + r) * N + colBase + c);
        }
        __syncthreads();

#pragma unroll
        for (int kk = 0; kk < BK; kk++) {
            float a[TM], b[TN];
#pragma unroll
            for (int i = 0; i < TM; i++) a[i] = As[kk][tr * TM + i];
#pragma unroll
            for (int j = 0; j < TN; j++) b[j] = Bs[kk][tc * TN + j];
#pragma unroll
            for (int i = 0; i < TM; i++)
#pragma unroll
                for (int j = 0; j < TN; j++)
                    acc[i][j] += a[i] * b[j];
        }
        __syncthreads();
    }

#pragma unroll
    for (int i = 0; i < TM; i++) {
        int gr = rowBase + tr * TM + i;
        if (gr >= M) continue;
        float* cp = C + (size_t)gr * N + colBase + tc * TN;
#pragma unroll
        for (int j = 0; j < TN; j += 4) {
            float4 v;
            v.x = acc[i][j + 0]; v.y = acc[i][j + 1];
            v.z = acc[i][j + 2]; v.w = acc[i][j + 3];
            if (bias) {
                int gc = colBase + tc * TN + j;
                v.x += bias[gc + 0]; v.y += bias[gc + 1];
                v.z += bias[gc + 2]; v.w += bias[gc + 3];
            }
            *reinterpret_cast<float4*>(cp + j) = v;
        }
    }
}

// ---------------- launch ----------------
extern "C" void kernel_launch(void* const* d_in, const int* in_sizes, int n_in,
                              void* d_out, int out_size) {
    const float* x    = (const float*)d_in[0];
    const int*   hidx = (const int*)d_in[1];   // int32 on device (JAX x64 disabled)
    const float* W1   = (const float*)d_in[2];
    const float* b1   = (const float*)d_in[3];
    const float* W2   = (const float*)d_in[4];
    const float* b2   = (const float*)d_in[5];
    const float* Wp   = (const float*)d_in[6];
    const float* bp   = (const float*)d_in[7];

    int nnz = in_sizes[1] / 2;
    const int* node_idx = hidx;
    const int* edge_idx = hidx + nnz;

    // output layout: (z [N,64], features_1 [N,128], features_2 [N,64])
    float* z  = (float*)d_out;
    float* f1 = z  + (size_t)N_NODES * OUT_C;
    float* f2 = f1 + (size_t)N_NODES * HID_C;

    float *p_h0, *p_m, *p_h1, *p_dinv, *p_binv;
    int *p_cnt, *p_eoff, *p_noff, *p_eadj, *p_nadj;
    cudaGetSymbolAddress((void**)&p_h0,   g_h0);
    cudaGetSymbolAddress((void**)&p_m,    g_m);
    cudaGetSymbolAddress((void**)&p_h1,   g_h1);
    cudaGetSymbolAddress((void**)&p_dinv, g_dinv);
    cudaGetSymbolAddress((void**)&p_binv, g_binv);
    cudaGetSymbolAddress((void**)&p_cnt,  g_cnt);
    cudaGetSymbolAddress((void**)&p_eoff, g_eoff);
    cudaGetSymbolAddress((void**)&p_noff, g_noff);
    cudaGetSymbolAddress((void**)&p_eadj, g_eadj);
    cudaGetSymbolAddress((void**)&p_nadj, g_nadj);

    int* p_ecnt = p_cnt;
    int* p_ncnt = p_cnt + N_EDGES;
    int* p_ecur = p_cnt + 2 * N_EDGES;
    int* p_ncur = p_cnt + 3 * N_EDGES;

    // ---- CSR build ----
    cudaMemsetAsync(p_cnt, 0, 4 * N_EDGES * sizeof(int));
    hist_kernel<<<(nnz + 255) / 256, 256>>>(node_idx, edge_idx, p_ncnt, p_ecnt, nnz);
    scan_kernel<<<2, 1024>>>(p_ecnt, p_eoff, p_ncnt, p_noff, p_binv, p_dinv, N_EDGES);
    fill_kernel<<<(nnz + 255) / 256, 256>>>(node_idx, edge_idx, p_eoff, p_noff,
                                            p_ecur, p_ncur, p_eadj, p_nadj, nnz);

    // ---- layer 1: h0 = x @ W1 ---- (M=50000, N=128, K=256)
    {
        dim3 grid((N_NODES + 63) / 64, HID_C / 64);
        sgemm_kernel<<<grid, 256>>>(x, W1, p_h0, N_NODES, HID_C, IN_C, nullptr);
    }
    // node -> edge (C=128), then edge -> node fused with Dinv/bias/relu
    {
        int blocks = (N_EDGES * 32 + 255) / 256;
        agg_kernel<4, false, false><<<blocks, 256>>>(p_h0, p_eadj, p_eoff, nullptr,
                                                     p_m, nullptr, nullptr, N_EDGES);
        agg_kernel<4, true, true><<<blocks, 256>>>(p_m, p_nadj, p_noff, p_binv,
                                                   f1, p_dinv, b1, N_NODES);
    }

    // ---- layer 2: h1 = f1 @ W2 ---- (M=50000, N=64, K=128)
    {
        dim3 grid((N_NODES + 127) / 128, OUT_C / 64);
        gemm_tpl<128, 64, 16, 8, 4><<<grid, 256>>>(f1, W2, p_h1, N_NODES, HID_C, nullptr);
    }
    {
        int blocks = (N_EDGES * 32 + 255) / 256;
        agg_kernel<2, false, false><<<blocks, 256>>>(p_h1, p_eadj, p_eoff, nullptr,
                                                     p_m, nullptr, nullptr, N_EDGES);
        agg_kernel<2, true, true><<<blocks, 256>>>(p_m, p_nadj, p_noff, p_binv,
                                                   f2, p_dinv, b2, N_NODES);
    }

    // ---- projection: z = f2 @ Wp + bp ---- (M=50000, N=64, K=64)
    {
        dim3 grid((N_NODES + 127) / 128, OUT_C / 64);
        gemm_tpl<128, 64, 16, 8, 4><<<grid, 256>>>(f2, Wp, z, N_NODES, OUT_C, bp);
    }
}

// round 7
// speedup vs baseline: 1.5442x; 1.5442x over previous
#include <cuda_runtime.h>
#include <cuda_fp16.h>
#include <stdint.h>

#define N_NODES 50000
#define N_EDGES 50000
#define IN_C 256
#define HID_C 128
#define OUT_C 64
#define MAX_NNZ 800000

// ---------------- scratch (no allocations allowed) ----------------
__device__ __half g_h0h[(size_t)N_NODES * HID_C];  // x @ W1, fp16
__device__ __half g_h1h[(size_t)N_NODES * OUT_C];  // f1 @ W2, fp16
__device__ float  g_m [(size_t)N_EDGES * HID_C];   // edge aggregation buffer (fp32)
__device__ float  g_dinv[N_NODES];
__device__ float  g_binv[N_EDGES];

// one contiguous block: [ecnt | ncnt | ecur | ncur] -> single memset
__device__ int g_cnt[4 * N_EDGES];
__device__ int g_eoff[N_EDGES + 1];
__device__ int g_noff[N_NODES + 1];
__device__ int g_eadj[MAX_NNZ];   // per edge-row: node indices
__device__ int g_nadj[MAX_NNZ];   // per node-row: edge indices

// ---------------- histogram ----------------
__global__ void hist_kernel(const int* __restrict__ node_idx,
                            const int* __restrict__ edge_idx,
                            int* __restrict__ ncnt, int* __restrict__ ecnt, int nnz) {
    int t = blockIdx.x * blockDim.x + threadIdx.x;
    if (t < nnz) {
        atomicAdd(&ncnt[node_idx[t]], 1);
        atomicAdd(&ecnt[edge_idx[t]], 1);
    }
}

// ---------------- exclusive scan over 50k ints + fused 1/count ----------------
__global__ void scan_kernel(const int* __restrict__ cntE, int* __restrict__ offE,
                            const int* __restrict__ cntN, int* __restrict__ offN,
                            float* __restrict__ binv, float* __restrict__ dinv, int n) {
    const int* cnt = (blockIdx.x == 0) ? cntE : cntN;
    int* off       = (blockIdx.x == 0) ? offE : offN;
    float* inv     = (blockIdx.x == 0) ? binv : dinv;
    __shared__ int sh[1024];
    int tid = threadIdx.x;
    int chunk = (n + 1023) / 1024;
    int start = tid * chunk;
    int end = min(start + chunk, n);
    int s = 0;
    for (int i = start; i < end; i++) {
        int c = cnt[i];
        s += c;
        inv[i] = (c > 0) ? (1.0f / (float)c) : 0.0f;
    }
    sh[tid] = s;
    __syncthreads();
    for (int d = 1; d < 1024; d <<= 1) {
        int v = (tid >= d) ? sh[tid - d] : 0;
        __syncthreads();
        sh[tid] += v;
        __syncthreads();
    }
    int run = (tid == 0) ? 0 : sh[tid - 1];
    for (int i = start; i < end; i++) {
        off[i] = run;
        run += cnt[i];
    }
    if (tid == 1023) off[n] = sh[1023];
}

// ---------------- CSR fill ----------------
__global__ void fill_kernel(const int* __restrict__ node_idx, const int* __restrict__ edge_idx,
                            const int* __restrict__ eoff, const int* __restrict__ noff,
                            int* __restrict__ ecur, int* __restrict__ ncur,
                            int* __restrict__ eadj, int* __restrict__ nadj, int nnz) {
    int t = blockIdx.x * blockDim.x + threadIdx.x;
    if (t < nnz) {
        int nd = node_idx[t];
        int eg = edge_idx[t];
        int p = atomicAdd(&ecur[eg], 1);
        eadj[eoff[eg] + p] = nd;
        int q = atomicAdd(&ncur[nd], 1);
        nadj[noff[nd] + q] = eg;
    }
}

// ---------------- pass 1: warp-per-row gather of fp16 src -> fp32 out ----------------
// out[row] = sum over nb of src_fp16[nb];  C = 32*VEC channels.
template <int VEC>
__global__ void agg_h_kernel(const __half* __restrict__ src, const int* __restrict__ adj,
                             const int* __restrict__ off, float* __restrict__ out, int rows) {
    int warp = (blockIdx.x * blockDim.x + threadIdx.x) >> 5;
    int lane = threadIdx.x & 31;
    if (warp >= rows) return;
    const int C = 32 * VEC;
    int s0 = off[warp];
    int s1 = off[warp + 1];

    float acc[VEC];
#pragma unroll
    for (int k = 0; k < VEC; k++) acc[k] = 0.0f;

    for (int j = s0; j < s1; j++) {
        int nb = adj[j];
        const __half2* p = reinterpret_cast<const __half2*>(src + (size_t)nb * C) + lane * (VEC / 2);
        if (VEC == 4) {
            __half2 a = p[0], b = p[1];
            float2 fa = __half22float2(a);
            float2 fb = __half22float2(b);
            acc[0] += fa.x; acc[1] += fa.y;
            acc[2] += fb.x; acc[3] += fb.y;
        } else {
            float2 fa = __half22float2(p[0]);
            acc[0] += fa.x; acc[1] += fa.y;
        }
    }

    float* q = out + (size_t)warp * C + lane * VEC;
    if (VEC == 4) {
        *reinterpret_cast<float4*>(q) = make_float4(acc[0], acc[1], acc[2], acc[3]);
    } else {
        *reinterpret_cast<float2*>(q) = make_float2(acc[0], acc[1]);
    }
}

// ---------------- pass 2: warp-per-row gather of fp32 m (scaled) -> fp32 final ----------------
// out[row] = relu( (sum nb: m[nb]*binv[nb]) * dinv[row] + bias )
template <int VEC>
__global__ void agg_f_kernel(const float* __restrict__ src, const int* __restrict__ adj,
                             const int* __restrict__ off, const float* __restrict__ sscale,
                             float* __restrict__ out, const float* __restrict__ rscale,
                             const float* __restrict__ bias, int rows) {
    int warp = (blockIdx.x * blockDim.x + threadIdx.x) >> 5;
    int lane = threadIdx.x & 31;
    if (warp >= rows) return;
    const int C = 32 * VEC;
    int s0 = off[warp];
    int s1 = off[warp + 1];

    float acc[VEC];
#pragma unroll
    for (int k = 0; k < VEC; k++) acc[k] = 0.0f;

    for (int j = s0; j < s1; j++) {
        int nb = adj[j];
        float sc = sscale[nb];
        const float* p = src + (size_t)nb * C + lane * VEC;
        if (VEC == 4) {
            float4 v = *reinterpret_cast<const float4*>(p);
            acc[0] += v.x * sc; acc[1] += v.y * sc;
            acc[2] += v.z * sc; acc[3] += v.w * sc;
        } else {
            float2 v = *reinterpret_cast<const float2*>(p);
            acc[0] += v.x * sc; acc[1] += v.y * sc;
        }
    }

    float rs = rscale[warp];
#pragma unroll
    for (int k = 0; k < VEC; k++)
        acc[k] = fmaxf(acc[k] * rs + bias[lane * VEC + k], 0.0f);

    float* q = out + (size_t)warp * C + lane * VEC;
    if (VEC == 4) {
        *reinterpret_cast<float4*>(q) = make_float4(acc[0], acc[1], acc[2], acc[3]);
    } else {
        *reinterpret_cast<float2*>(q) = make_float2(acc[0], acc[1]);
    }
}

// ---------------- proven 64x64x16 fp32 GEMM; fp16 or fp32(+bias) output ----------------
template <bool HALF_OUT>
__global__ void sgemm_kernel(const float* __restrict__ A, const float* __restrict__ B,
                             void* __restrict__ Cv, int M, int N, int K,
                             const float* __restrict__ bias) {
    const int BM = 64, BN = 64, BK = 16;
    __shared__ float As[BK][BM + 1];
    __shared__ float Bs[BK][BN];

    int tid = threadIdx.x;
    int tr = tid / 16;
    int tc = tid % 16;
    int rowBase = blockIdx.x * BM;
    int colBase = blockIdx.y * BN;

    float acc[4][4] = {};

    for (int k0 = 0; k0 < K; k0 += BK) {
#pragma unroll
        for (int i = 0; i < 4; i++) {
            int linear = tid + i * 256;
            int r = linear / BK;
            int c = linear % BK;
            int gr = rowBase + r;
            As[c][r] = (gr < M) ? A[(size_t)gr * K + k0 + c] : 0.0f;
        }
#pragma unroll
        for (int i = 0; i < 4; i++) {
            int linear = tid + i * 256;
            int r = linear / BN;
            int c = linear % BN;
            Bs[r][c] = B[(size_t)(k0 + r) * N + colBase + c];
        }
        __syncthreads();

#pragma unroll
        for (int kk = 0; kk < BK; kk++) {
            float a[4], b[4];
#pragma unroll
            for (int i = 0; i < 4; i++) a[i] = As[kk][tr * 4 + i];
#pragma unroll
            for (int j = 0; j < 4; j++) b[j] = Bs[kk][tc * 4 + j];
#pragma unroll
            for (int i = 0; i < 4; i++)
#pragma unroll
                for (int j = 0; j < 4; j++)
                    acc[i][j] += a[i] * b[j];
        }
        __syncthreads();
    }

#pragma unroll
    for (int i = 0; i < 4; i++) {
        int gr = rowBase + tr * 4 + i;
        if (gr >= M) continue;
        int gc = colBase + tc * 4;
        if (HALF_OUT) {
            __half* C = (__half*)Cv;
            __half2 h01 = __floats2half2_rn(acc[i][0], acc[i][1]);
            __half2 h23 = __floats2half2_rn(acc[i][2], acc[i][3]);
            __half2* cp = reinterpret_cast<__half2*>(C + (size_t)gr * N + gc);
            cp[0] = h01;
            cp[1] = h23;
        } else {
            float* C = (float*)Cv;
#pragma unroll
            for (int j = 0; j < 4; j++) {
                float v = acc[i][j];
                if (bias) v += bias[gc + j];
                C[(size_t)gr * N + gc + j] = v;
            }
        }
    }
}

// ---------------- launch ----------------
extern "C" void kernel_launch(void* const* d_in, const int* in_sizes, int n_in,
                              void* d_out, int out_size) {
    const float* x    = (const float*)d_in[0];
    const int*   hidx = (const int*)d_in[1];   // int32 on device (JAX x64 disabled)
    const float* W1   = (const float*)d_in[2];
    const float* b1   = (const float*)d_in[3];
    const float* W2   = (const float*)d_in[4];
    const float* b2   = (const float*)d_in[5];
    const float* Wp   = (const float*)d_in[6];
    const float* bp   = (const float*)d_in[7];

    int nnz = in_sizes[1] / 2;
    const int* node_idx = hidx;
    const int* edge_idx = hidx + nnz;

    // output layout: (z [N,64], features_1 [N,128], features_2 [N,64])
    float* z  = (float*)d_out;
    float* f1 = z  + (size_t)N_NODES * OUT_C;
    float* f2 = f1 + (size_t)N_NODES * HID_C;

    __half *p_h0h, *p_h1h;
    float *p_m, *p_dinv, *p_binv;
    int *p_cnt, *p_eoff, *p_noff, *p_eadj, *p_nadj;
    cudaGetSymbolAddress((void**)&p_h0h,  g_h0h);
    cudaGetSymbolAddress((void**)&p_h1h,  g_h1h);
    cudaGetSymbolAddress((void**)&p_m,    g_m);
    cudaGetSymbolAddress((void**)&p_dinv, g_dinv);
    cudaGetSymbolAddress((void**)&p_binv, g_binv);
    cudaGetSymbolAddress((void**)&p_cnt,  g_cnt);
    cudaGetSymbolAddress((void**)&p_eoff, g_eoff);
    cudaGetSymbolAddress((void**)&p_noff, g_noff);
    cudaGetSymbolAddress((void**)&p_eadj, g_eadj);
    cudaGetSymbolAddress((void**)&p_nadj, g_nadj);

    int* p_ecnt = p_cnt;
    int* p_ncnt = p_cnt + N_EDGES;
    int* p_ecur = p_cnt + 2 * N_EDGES;
    int* p_ncur = p_cnt + 3 * N_EDGES;

    // ---- CSR build ----
    cudaMemsetAsync(p_cnt, 0, 4 * N_EDGES * sizeof(int));
    hist_kernel<<<(nnz + 255) / 256, 256>>>(node_idx, edge_idx, p_ncnt, p_ecnt, nnz);
    scan_kernel<<<2, 1024>>>(p_ecnt, p_eoff, p_ncnt, p_noff, p_binv, p_dinv, N_EDGES);
    fill_kernel<<<(nnz + 255) / 256, 256>>>(node_idx, edge_idx, p_eoff, p_noff,
                                            p_ecur, p_ncur, p_eadj, p_nadj, nnz);

    int agg_blocks = (N_EDGES * 32 + 255) / 256;

    // ---- layer 1: h0 = x @ W1 (fp16 out) ----
    {
        dim3 grid((N_NODES + 63) / 64, HID_C / 64);
        sgemm_kernel<true><<<grid, 256>>>(x, W1, p_h0h, N_NODES, HID_C, IN_C, nullptr);
    }
    agg_h_kernel<4><<<agg_blocks, 256>>>(p_h0h, p_eadj, p_eoff, p_m, N_EDGES);
    agg_f_kernel<4><<<agg_blocks, 256>>>(p_m, p_nadj, p_noff, p_binv,
                                         f1, p_dinv, b1, N_NODES);

    // ---- layer 2: h1 = f1 @ W2 (fp16 out) ----
    {
        dim3 grid((N_NODES + 63) / 64, OUT_C / 64);
        sgemm_kernel<true><<<grid, 256>>>(f1, W2, p_h1h, N_NODES, OUT_C, HID_C, nullptr);
    }
    agg_h_kernel<2><<<agg_blocks, 256>>>(p_h1h, p_eadj, p_eoff, p_m, N_EDGES);
    agg_f_kernel<2><<<agg_blocks, 256>>>(p_m, p_nadj, p_noff, p_binv,
                                         f2, p_dinv, b2, N_NODES);

    // ---- projection: z = f2 @ Wp + bp (fp32 out) ----
    {
        dim3 grid((N_NODES + 63) / 64, OUT_C / 64);
        sgemm_kernel<false><<<grid, 256>>>(f2, Wp, z, N_NODES, OUT_C, OUT_C, bp);
    }
}

// round 8
// speedup vs baseline: 1.5805x; 1.0235x over previous
#include <cuda_runtime.h>
#include <stdint.h>

#define N_NODES 50000
#define N_EDGES 50000
#define IN_C 256
#define HID_C 128
#define OUT_C 64
#define MAX_NNZ 800000

// ---------------- scratch (no allocations allowed) ----------------
__device__ float g_h0[(size_t)N_NODES * HID_C];   // x @ W1
__device__ float g_m [(size_t)N_EDGES * HID_C];   // edge aggregation buffer (reused at C=64)
__device__ float g_h1[(size_t)N_NODES * OUT_C];   // f1 @ W2
__device__ float g_dinv[N_NODES];
__device__ float g_binv[N_EDGES];

__device__ int g_cnt[4 * N_EDGES];   // [ecnt | ncnt | ecur | ncur]
__device__ int g_eoff[N_EDGES + 1];
__device__ int g_noff[N_NODES + 1];
__device__ int g_eadj[MAX_NNZ];
__device__ int g_nadj[MAX_NNZ];

// ---------------- histogram ----------------
__global__ void hist_kernel(const int* __restrict__ node_idx,
                            const int* __restrict__ edge_idx,
                            int* __restrict__ ncnt, int* __restrict__ ecnt, int nnz) {
    int t = blockIdx.x * blockDim.x + threadIdx.x;
    if (t < nnz) {
        atomicAdd(&ncnt[node_idx[t]], 1);
        atomicAdd(&ecnt[edge_idx[t]], 1);
    }
}

// ---------------- exclusive scan + fused 1/count ----------------
__global__ void scan_kernel(const int* __restrict__ cntE, int* __restrict__ offE,
                            const int* __restrict__ cntN, int* __restrict__ offN,
                            float* __restrict__ binv, float* __restrict__ dinv, int n) {
    const int* cnt = (blockIdx.x == 0) ? cntE : cntN;
    int* off       = (blockIdx.x == 0) ? offE : offN;
    float* inv     = (blockIdx.x == 0) ? binv : dinv;
    __shared__ int sh[1024];
    int tid = threadIdx.x;
    int chunk = (n + 1023) / 1024;
    int start = tid * chunk;
    int end = min(start + chunk, n);
    int s = 0;
    for (int i = start; i < end; i++) {
        int c = cnt[i];
        s += c;
        inv[i] = (c > 0) ? (1.0f / (float)c) : 0.0f;
    }
    sh[tid] = s;
    __syncthreads();
    for (int d = 1; d < 1024; d <<= 1) {
        int v = (tid >= d) ? sh[tid - d] : 0;
        __syncthreads();
        sh[tid] += v;
        __syncthreads();
    }
    int run = (tid == 0) ? 0 : sh[tid - 1];
    for (int i = start; i < end; i++) {
        off[i] = run;
        run += cnt[i];
    }
    if (tid == 1023) off[n] = sh[1023];
}

// ---------------- CSR fill ----------------
__global__ void fill_kernel(const int* __restrict__ node_idx, const int* __restrict__ edge_idx,
                            const int* __restrict__ eoff, const int* __restrict__ noff,
                            int* __restrict__ ecur, int* __restrict__ ncur,
                            int* __restrict__ eadj, int* __restrict__ nadj, int nnz) {
    int t = blockIdx.x * blockDim.x + threadIdx.x;
    if (t < nnz) {
        int nd = node_idx[t];
        int eg = edge_idx[t];
        int p = atomicAdd(&ecur[eg], 1);
        eadj[eoff[eg] + p] = nd;
        int q = atomicAdd(&ncur[nd], 1);
        nadj[noff[nd] + q] = eg;
    }
}

// ---------------- warp-per-row gather-reduce (fp32, proven R4 version) ----------------
template <int VEC, bool SRC_SCALE, bool FINAL>
__global__ void agg_kernel(const float* __restrict__ src, const int* __restrict__ adj,
                           const int* __restrict__ off, const float* __restrict__ sscale,
                           float* __restrict__ out, const float* __restrict__ rscale,
                           const float* __restrict__ bias, int rows) {
    int warp = (blockIdx.x * blockDim.x + threadIdx.x) >> 5;
    int lane = threadIdx.x & 31;
    if (warp >= rows) return;
    const int C = 32 * VEC;
    int s0 = off[warp];
    int s1 = off[warp + 1];

    float acc[VEC];
#pragma unroll
    for (int k = 0; k < VEC; k++) acc[k] = 0.0f;

    for (int j = s0; j < s1; j++) {
        int nb = adj[j];
        float sc = SRC_SCALE ? sscale[nb] : 1.0f;
        const float* p = src + (size_t)nb * C + lane * VEC;
        if (VEC == 4) {
            float4 v = *reinterpret_cast<const float4*>(p);
            acc[0] += v.x * sc; acc[1] += v.y * sc;
            acc[2] += v.z * sc; acc[3] += v.w * sc;
        } else {
            float2 v = *reinterpret_cast<const float2*>(p);
            acc[0] += v.x * sc; acc[1] += v.y * sc;
        }
    }

    float* q = out + (size_t)warp * C + lane * VEC;
    if (FINAL) {
        float rs = rscale[warp];
#pragma unroll
        for (int k = 0; k < VEC; k++)
            acc[k] = fmaxf(acc[k] * rs + bias[lane * VEC + k], 0.0f);
    }
    if (VEC == 4) {
        *reinterpret_cast<float4*>(q) = make_float4(acc[0], acc[1], acc[2], acc[3]);
    } else {
        *reinterpret_cast<float2*>(q) = make_float2(acc[0], acc[1]);
    }
}

// ---------------- TF32 tensor-core GEMM with 3xTF32 split ----------------
__device__ __forceinline__ uint32_t f2tf32(float x) {
    uint32_t r;
    asm("cvt.rna.tf32.f32 %0, %1;" : "=r"(r) : "f"(x));
    return r;
}

__device__ __forceinline__ void mma_tf32(float* c, const uint32_t* a, const uint32_t* b) {
    asm("mma.sync.aligned.m16n8k8.row.col.f32.tf32.tf32.f32 "
        "{%0,%1,%2,%3}, {%4,%5,%6,%7}, {%8,%9}, {%0,%1,%2,%3};"
        : "+f"(c[0]), "+f"(c[1]), "+f"(c[2]), "+f"(c[3])
        : "r"(a[0]), "r"(a[1]), "r"(a[2]), "r"(a[3]), "r"(b[0]), "r"(b[1]));
}

// C[M,N] = A[M,K] @ B[K,N] (+bias). BM=128, BN=64, BK=32, 256 threads (8 warps, 4x2).
// Requires: N multiple of 64, K multiple of 32.
__global__ void __launch_bounds__(256)
tf32_gemm(const float* __restrict__ A, const float* __restrict__ B,
          float* __restrict__ C, int M, int N, int K,
          const float* __restrict__ bias) {
    const int BM = 128, BN = 64, BK = 32;
    __shared__ float As[BK][BM + 8];   // [k][m], stride 136: conflict-free frag reads
    __shared__ float Bs[BK][BN + 8];   // [k][n], stride 72

    int tid = threadIdx.x;
    int wid = tid >> 5;
    int lane = tid & 31;
    int gid = lane >> 2;       // groupID 0..7
    int tg = lane & 3;         // threadID_in_group 0..3
    int warp_m = wid >> 1;     // 0..3
    int warp_n = wid & 1;      // 0..1
    int mb = warp_m * 32;
    int nb = warp_n * 32;

    int rowBase = blockIdx.x * BM;
    int colBase = blockIdx.y * BN;

    float acc[2][4][4];
#pragma unroll
    for (int t = 0; t < 2; t++)
#pragma unroll
        for (int u = 0; u < 4; u++)
#pragma unroll
            for (int k = 0; k < 4; k++) acc[t][u][k] = 0.0f;

    for (int k0 = 0; k0 < K; k0 += BK) {
        // A tile: BM x BK -> As[k][m] (transposed). 4096 elems, 4 float4/thread.
#pragma unroll
        for (int it = 0; it < 4; it++) {
            int idx = tid * 4 + it * 1024;
            int r = idx / BK;
            int c = idx % BK;
            int gr = rowBase + r;
            float4 v = make_float4(0.f, 0.f, 0.f, 0.f);
            if (gr < M)
                v = *reinterpret_cast<const float4*>(A + (size_t)gr * K + k0 + c);
            As[c + 0][r] = v.x;
            As[c + 1][r] = v.y;
            As[c + 2][r] = v.z;
            As[c + 3][r] = v.w;
        }
        // B tile: BK x BN. 2048 elems, 2 float4/thread.
#pragma unroll
        for (int it = 0; it < 2; it++) {
            int idx = tid * 4 + it * 1024;
            int r = idx / BN;
            int c = idx % BN;
            *reinterpret_cast<float4*>(&Bs[r][c]) =
                *reinterpret_cast<const float4*>(B + (size_t)(k0 + r) * N + colBase + c);
        }
        __syncthreads();

#pragma unroll
        for (int ks = 0; ks < 4; ks++) {
            int k = ks * 8;
            // A fragments (2 m16 tiles), split hi/lo
            uint32_t ahi[2][4], alo[2][4];
#pragma unroll
            for (int t = 0; t < 2; t++) {
                int m = mb + t * 16 + gid;
                float av[4];
                av[0] = As[k + tg][m];
                av[1] = As[k + tg][m + 8];
                av[2] = As[k + tg + 4][m];
                av[3] = As[k + tg + 4][m + 8];
#pragma unroll
                for (int q = 0; q < 4; q++) {
                    uint32_t h = f2tf32(av[q]);
                    ahi[t][q] = h;
                    alo[t][q] = f2tf32(av[q] - __uint_as_float(h));
                }
            }
            // B fragments (4 n8 tiles), split hi/lo
            uint32_t bhi[4][2], blo[4][2];
#pragma unroll
            for (int u = 0; u < 4; u++) {
                int n = nb + u * 8 + gid;
                float bv[2];
                bv[0] = Bs[k + tg][n];
                bv[1] = Bs[k + tg + 4][n];
#pragma unroll
                for (int q = 0; q < 2; q++) {
                    uint32_t h = f2tf32(bv[q]);
                    bhi[u][q] = h;
                    blo[u][q] = f2tf32(bv[q] - __uint_as_float(h));
                }
            }
            // 3xTF32: hi*hi + lo*hi + hi*lo
#pragma unroll
            for (int t = 0; t < 2; t++)
#pragma unroll
                for (int u = 0; u < 4; u++) {
                    mma_tf32(acc[t][u], ahi[t], bhi[u]);
                    mma_tf32(acc[t][u], alo[t], bhi[u]);
                    mma_tf32(acc[t][u], ahi[t], blo[u]);
                }
        }
        __syncthreads();
    }

    // store: c0,c1 -> (row, col + tg*2), c2,c3 -> (row+8, ...)
#pragma unroll
    for (int t = 0; t < 2; t++) {
#pragma unroll
        for (int u = 0; u < 4; u++) {
            int row = rowBase + mb + t * 16 + gid;
            int col = colBase + nb + u * 8 + tg * 2;
            float b0 = 0.f, b1 = 0.f;
            if (bias) { b0 = bias[col]; b1 = bias[col + 1]; }
            if (row < M) {
                float2 v = make_float2(acc[t][u][0] + b0, acc[t][u][1] + b1);
                *reinterpret_cast<float2*>(C + (size_t)row * N + col) = v;
            }
            if (row + 8 < M) {
                float2 v = make_float2(acc[t][u][2] + b0, acc[t][u][3] + b1);
                *reinterpret_cast<float2*>(C + (size_t)(row + 8) * N + col) = v;
            }
        }
    }
}

// ---------------- launch ----------------
extern "C" void kernel_launch(void* const* d_in, const int* in_sizes, int n_in,
                              void* d_out, int out_size) {
    const float* x    = (const float*)d_in[0];
    const int*   hidx = (const int*)d_in[1];   // int32 on device (JAX x64 disabled)
    const float* W1   = (const float*)d_in[2];
    const float* b1   = (const float*)d_in[3];
    const float* W2   = (const float*)d_in[4];
    const float* b2   = (const float*)d_in[5];
    const float* Wp   = (const float*)d_in[6];
    const float* bp   = (const float*)d_in[7];

    int nnz = in_sizes[1] / 2;
    const int* node_idx = hidx;
    const int* edge_idx = hidx + nnz;

    // output layout: (z [N,64], features_1 [N,128], features_2 [N,64])
    float* z  = (float*)d_out;
    float* f1 = z  + (size_t)N_NODES * OUT_C;
    float* f2 = f1 + (size_t)N_NODES * HID_C;

    float *p_h0, *p_m, *p_h1, *p_dinv, *p_binv;
    int *p_cnt, *p_eoff, *p_noff, *p_eadj, *p_nadj;
    cudaGetSymbolAddress((void**)&p_h0,   g_h0);
    cudaGetSymbolAddress((void**)&p_m,    g_m);
    cudaGetSymbolAddress((void**)&p_h1,   g_h1);
    cudaGetSymbolAddress((void**)&p_dinv, g_dinv);
    cudaGetSymbolAddress((void**)&p_binv, g_binv);
    cudaGetSymbolAddress((void**)&p_cnt,  g_cnt);
    cudaGetSymbolAddress((void**)&p_eoff, g_eoff);
    cudaGetSymbolAddress((void**)&p_noff, g_noff);
    cudaGetSymbolAddress((void**)&p_eadj, g_eadj);
    cudaGetSymbolAddress((void**)&p_nadj, g_nadj);

    int* p_ecnt = p_cnt;
    int* p_ncnt = p_cnt + N_EDGES;
    int* p_ecur = p_cnt + 2 * N_EDGES;
    int* p_ncur = p_cnt + 3 * N_EDGES;

    // ---- CSR build ----
    cudaMemsetAsync(p_cnt, 0, 4 * N_EDGES * sizeof(int));
    hist_kernel<<<(nnz + 255) / 256, 256>>>(node_idx, edge_idx, p_ncnt, p_ecnt, nnz);
    scan_kernel<<<2, 1024>>>(p_ecnt, p_eoff, p_ncnt, p_noff, p_binv, p_dinv, N_EDGES);
    fill_kernel<<<(nnz + 255) / 256, 256>>>(node_idx, edge_idx, p_eoff, p_noff,
                                            p_ecur, p_ncur, p_eadj, p_nadj, nnz);

    int agg_blocks = (N_EDGES * 32 + 255) / 256;
    dim3 ggrid((N_NODES + 127) / 128, 1);

    // ---- layer 1: h0 = x @ W1 ---- (M=50000, N=128, K=256)
    {
        dim3 grid((N_NODES + 127) / 128, HID_C / 64);
        tf32_gemm<<<grid, 256>>>(x, W1, p_h0, N_NODES, HID_C, IN_C, nullptr);
    }
    agg_kernel<4, false, false><<<agg_blocks, 256>>>(p_h0, p_eadj, p_eoff, nullptr,
                                                     p_m, nullptr, nullptr, N_EDGES);
    agg_kernel<4, true, true><<<agg_blocks, 256>>>(p_m, p_nadj, p_noff, p_binv,
                                                   f1, p_dinv, b1, N_NODES);

    // ---- layer 2: h1 = f1 @ W2 ---- (M=50000, N=64, K=128)
    tf32_gemm<<<ggrid, 256>>>(f1, W2, p_h1, N_NODES, OUT_C, HID_C, nullptr);
    agg_kernel<2, false, false><<<agg_blocks, 256>>>(p_h1, p_eadj, p_eoff, nullptr,
                                                     p_m, nullptr, nullptr, N_EDGES);
    agg_kernel<2, true, true><<<agg_blocks, 256>>>(p_m, p_nadj, p_noff, p_binv,
                                                   f2, p_dinv, b2, N_NODES);

    // ---- projection: z = f2 @ Wp + bp ---- (M=50000, N=64, K=64)
    tf32_gemm<<<ggrid, 256>>>(f2, Wp, z, N_NODES, OUT_C, OUT_C, bp);
}

// round 10
// speedup vs baseline: 1.6013x; 1.0131x over previous
#include <cuda_runtime.h>
#include <stdint.h>

#define N_NODES 50000
#define N_EDGES 50000
#define IN_C 256
#define HID_C 128
#define OUT_C 64
#define MAX_NNZ 800000

// ---------------- scratch (no allocations allowed) ----------------
__device__ float g_h0[(size_t)N_NODES * HID_C];   // x @ W1
__device__ float g_m [(size_t)N_EDGES * HID_C];   // edge aggregation buffer (reused at C=64)
__device__ float g_h1[(size_t)N_NODES * OUT_C];   // f1 @ W2
__device__ float g_dinv[N_NODES];
__device__ float g_binv[N_EDGES];

__device__ int g_cnt[4 * N_EDGES];   // [ecnt | ncnt | ecur | ncur]
__device__ int g_eoff[N_EDGES + 1];
__device__ int g_noff[N_NODES + 1];
__device__ int g_eadj[MAX_NNZ];
__device__ int g_nadj[MAX_NNZ];

// ---------------- histogram ----------------
__global__ void hist_kernel(const int* __restrict__ node_idx,
                            const int* __restrict__ edge_idx,
                            int* __restrict__ ncnt, int* __restrict__ ecnt, int nnz) {
    int t = blockIdx.x * blockDim.x + threadIdx.x;
    if (t < nnz) {
        atomicAdd(&ncnt[node_idx[t]], 1);
        atomicAdd(&ecnt[edge_idx[t]], 1);
    }
}

// ---------------- exclusive scan + fused 1/count ----------------
__global__ void scan_kernel(const int* __restrict__ cntE, int* __restrict__ offE,
                            const int* __restrict__ cntN, int* __restrict__ offN,
                            float* __restrict__ binv, float* __restrict__ dinv, int n) {
    const int* cnt = (blockIdx.x == 0) ? cntE : cntN;
    int* off       = (blockIdx.x == 0) ? offE : offN;
    float* inv     = (blockIdx.x == 0) ? binv : dinv;
    __shared__ int sh[1024];
    int tid = threadIdx.x;
    int chunk = (n + 1023) / 1024;
    int start = tid * chunk;
    int end = min(start + chunk, n);
    int s = 0;
    for (int i = start; i < end; i++) {
        int c = cnt[i];
        s += c;
        inv[i] = (c > 0) ? (1.0f / (float)c) : 0.0f;
    }
    sh[tid] = s;
    __syncthreads();
    for (int d = 1; d < 1024; d <<= 1) {
        int v = (tid >= d) ? sh[tid - d] : 0;
        __syncthreads();
        sh[tid] += v;
        __syncthreads();
    }
    int run = (tid == 0) ? 0 : sh[tid - 1];
    for (int i = start; i < end; i++) {
        off[i] = run;
        run += cnt[i];
    }
    if (tid == 1023) off[n] = sh[1023];
}

// ---------------- CSR fill ----------------
__global__ void fill_kernel(const int* __restrict__ node_idx, const int* __restrict__ edge_idx,
                            const int* __restrict__ eoff, const int* __restrict__ noff,
                            int* __restrict__ ecur, int* __restrict__ ncur,
                            int* __restrict__ eadj, int* __restrict__ nadj, int nnz) {
    int t = blockIdx.x * blockDim.x + threadIdx.x;
    if (t < nnz) {
        int nd = node_idx[t];
        int eg = edge_idx[t];
        int p = atomicAdd(&ecur[eg], 1);
        eadj[eoff[eg] + p] = nd;
        int q = atomicAdd(&ncur[nd], 1);
        nadj[noff[nd] + q] = eg;
    }
}

// ---------------- warp-per-row gather-reduce (fp32, proven R4 version) ----------------
template <int VEC, bool SRC_SCALE, bool FINAL>
__global__ void agg_kernel(const float* __restrict__ src, const int* __restrict__ adj,
                           const int* __restrict__ off, const float* __restrict__ sscale,
                           float* __restrict__ out, const float* __restrict__ rscale,
                           const float* __restrict__ bias, int rows) {
    int warp = (blockIdx.x * blockDim.x + threadIdx.x) >> 5;
    int lane = threadIdx.x & 31;
    if (warp >= rows) return;
    const int C = 32 * VEC;
    int s0 = off[warp];
    int s1 = off[warp + 1];

    float acc[VEC];
#pragma unroll
    for (int k = 0; k < VEC; k++) acc[k] = 0.0f;

    for (int j = s0; j < s1; j++) {
        int nb = adj[j];
        float sc = SRC_SCALE ? sscale[nb] : 1.0f;
        const float* p = src + (size_t)nb * C + lane * VEC;
        if (VEC == 4) {
            float4 v = *reinterpret_cast<const float4*>(p);
            acc[0] += v.x * sc; acc[1] += v.y * sc;
            acc[2] += v.z * sc; acc[3] += v.w * sc;
        } else {
            float2 v = *reinterpret_cast<const float2*>(p);
            acc[0] += v.x * sc; acc[1] += v.y * sc;
        }
    }

    float* q = out + (size_t)warp * C + lane * VEC;
    if (FINAL) {
        float rs = rscale[warp];
#pragma unroll
        for (int k = 0; k < VEC; k++)
            acc[k] = fmaxf(acc[k] * rs + bias[lane * VEC + k], 0.0f);
    }
    if (VEC == 4) {
        *reinterpret_cast<float4*>(q) = make_float4(acc[0], acc[1], acc[2], acc[3]);
    } else {
        *reinterpret_cast<float2*>(q) = make_float2(acc[0], acc[1]);
    }
}

// ---------------- 2xTF32 tensor-core GEMM (A split hi+lo, B single tf32) ----------------
__device__ __forceinline__ uint32_t f2tf32(float x) {
    uint32_t r;
    asm("cvt.rna.tf32.f32 %0, %1;" : "=r"(r) : "f"(x));
    return r;
}

__device__ __forceinline__ void mma_tf32(float* c, const uint32_t* a, const uint32_t* b) {
    asm("mma.sync.aligned.m16n8k8.row.col.f32.tf32.tf32.f32 "
        "{%0,%1,%2,%3}, {%4,%5,%6,%7}, {%8,%9}, {%0,%1,%2,%3};"
        : "+f"(c[0]), "+f"(c[1]), "+f"(c[2]), "+f"(c[3])
        : "r"(a[0]), "r"(a[1]), "r"(a[2]), "r"(a[3]), "r"(b[0]), "r"(b[1]));
}

// C[M,N] = A[M,K] @ B[K,N] (+bias). BM=128, BN=64, BK=32, 256 threads (8 warps, 4x2).
// All tf32 conversion done at smem-load time; inner loop is pure LDS + MMA.
// Requires: N multiple of 64, K multiple of 32.
__global__ void __launch_bounds__(256)
tf32_gemm(const float* __restrict__ A, const float* __restrict__ B,
          float* __restrict__ C, int M, int N, int K,
          const float* __restrict__ bias) {
    const int BM = 128, BN = 64, BK = 32;
    __shared__ uint32_t Ahi[BK][BM + 8];   // stride 136
    __shared__ uint32_t Alo[BK][BM + 8];
    __shared__ uint32_t Bs [BK][BN + 8];   // stride 72

    int tid = threadIdx.x;
    int wid = tid >> 5;
    int lane = tid & 31;
    int gid = lane >> 2;       // 0..7
    int tg = lane & 3;         // 0..3
    int warp_m = wid >> 1;     // 0..3
    int warp_n = wid & 1;      // 0..1
    int mb = warp_m * 32;
    int nb = warp_n * 32;

    int rowBase = blockIdx.x * BM;
    int colBase = blockIdx.y * BN;

    float acc[2][4][4];
#pragma unroll
    for (int t = 0; t < 2; t++)
#pragma unroll
        for (int u = 0; u < 4; u++)
#pragma unroll
            for (int k = 0; k < 4; k++) acc[t][u][k] = 0.0f;

    for (int k0 = 0; k0 < K; k0 += BK) {
        // A tile: BM x BK, split hi/lo at load. 4096 elems, 4 float4/thread.
#pragma unroll
        for (int it = 0; it < 4; it++) {
            int idx = tid * 4 + it * 1024;
            int r = idx / BK;
            int c = idx % BK;
            int gr = rowBase + r;
            float4 v = make_float4(0.f, 0.f, 0.f, 0.f);
            if (gr < M)
                v = *reinterpret_cast<const float4*>(A + (size_t)gr * K + k0 + c);
            float vv[4] = {v.x, v.y, v.z, v.w};
#pragma unroll
            for (int q = 0; q < 4; q++) {
                uint32_t h = f2tf32(vv[q]);
                Ahi[c + q][r] = h;
                Alo[c + q][r] = f2tf32(vv[q] - __uint_as_float(h));
            }
        }
        // B tile: BK x BN, single tf32 at load. 2048 elems, 2 float4/thread.
#pragma unroll
        for (int it = 0; it < 2; it++) {
            int idx = tid * 4 + it * 1024;
            int r = idx / BN;
            int c = idx % BN;
            float4 v = *reinterpret_cast<const float4*>(B + (size_t)(k0 + r) * N + colBase + c);
            Bs[r][c + 0] = f2tf32(v.x);
            Bs[r][c + 1] = f2tf32(v.y);
            Bs[r][c + 2] = f2tf32(v.z);
            Bs[r][c + 3] = f2tf32(v.w);
        }
        __syncthreads();

#pragma unroll
        for (int ks = 0; ks < 4; ks++) {
            int k = ks * 8;
            uint32_t ahi[2][4], alo[2][4];
#pragma unroll
            for (int t = 0; t < 2; t++) {
                int m = mb + t * 16 + gid;
                ahi[t][0] = Ahi[k + tg][m];
                ahi[t][1] = Ahi[k + tg][m + 8];
                ahi[t][2] = Ahi[k + tg + 4][m];
                ahi[t][3] = Ahi[k + tg + 4][m + 8];
                alo[t][0] = Alo[k + tg][m];
                alo[t][1] = Alo[k + tg][m + 8];
                alo[t][2] = Alo[k + tg + 4][m];
                alo[t][3] = Alo[k + tg + 4][m + 8];
            }
            uint32_t bf[4][2];
#pragma unroll
            for (int u = 0; u < 4; u++) {
                int n = nb + u * 8 + gid;
                bf[u][0] = Bs[k + tg][n];
                bf[u][1] = Bs[k + tg + 4][n];
            }
#pragma unroll
            for (int t = 0; t < 2; t++)
#pragma unroll
                for (int u = 0; u < 4; u++) {
                    mma_tf32(acc[t][u], ahi[t], bf[u]);
                    mma_tf32(acc[t][u], alo[t], bf[u]);
                }
        }
        __syncthreads();
    }

#pragma unroll
    for (int t = 0; t < 2; t++) {
#pragma unroll
        for (int u = 0; u < 4; u++) {
            int row = rowBase + mb + t * 16 + gid;
            int col = colBase + nb + u * 8 + tg * 2;
            float b0 = 0.f, b1 = 0.f;
            if (bias) { b0 = bias[col]; b1 = bias[col + 1]; }
            if (row < M) {
                float2 v = make_float2(acc[t][u][0] + b0, acc[t][u][1] + b1);
                *reinterpret_cast<float2*>(C + (size_t)row * N + col) = v;
            }
            if (row + 8 < M) {
                float2 v = make_float2(acc[t][u][2] + b0, acc[t][u][3] + b1);
                *reinterpret_cast<float2*>(C + (size_t)(row + 8) * N + col) = v;
            }
        }
    }
}

// ---------------- launch ----------------
extern "C" void kernel_launch(void* const* d_in, const int* in_sizes, int n_in,
                              void* d_out, int out_size) {
    const float* x    = (const float*)d_in[0];
    const int*   hidx = (const int*)d_in[1];   // int32 on device (JAX x64 disabled)
    const float* W1   = (const float*)d_in[2];
    const float* b1   = (const float*)d_in[3];
    const float* W2   = (const float*)d_in[4];
    const float* b2   = (const float*)d_in[5];
    const float* Wp   = (const float*)d_in[6];
    const float* bp   = (const float*)d_in[7];

    int nnz = in_sizes[1] / 2;
    const int* node_idx = hidx;
    const int* edge_idx = hidx + nnz;

    // output layout: (z [N,64], features_1 [N,128], features_2 [N,64])
    float* z  = (float*)d_out;
    float* f1 = z  + (size_t)N_NODES * OUT_C;
    float* f2 = f1 + (size_t)N_NODES * HID_C;

    float *p_h0, *p_m, *p_h1, *p_dinv, *p_binv;
    int *p_cnt, *p_eoff, *p_noff, *p_eadj, *p_nadj;
    cudaGetSymbolAddress((void**)&p_h0,   g_h0);
    cudaGetSymbolAddress((void**)&p_m,    g_m);
    cudaGetSymbolAddress((void**)&p_h1,   g_h1);
    cudaGetSymbolAddress((void**)&p_dinv, g_dinv);
    cudaGetSymbolAddress((void**)&p_binv, g_binv);
    cudaGetSymbolAddress((void**)&p_cnt,  g_cnt);
    cudaGetSymbolAddress((void**)&p_eoff, g_eoff);
    cudaGetSymbolAddress((void**)&p_noff, g_noff);
    cudaGetSymbolAddress((void**)&p_eadj, g_eadj);
    cudaGetSymbolAddress((void**)&p_nadj, g_nadj);

    int* p_ecnt = p_cnt;
    int* p_ncnt = p_cnt + N_EDGES;
    int* p_ecur = p_cnt + 2 * N_EDGES;
    int* p_ncur = p_cnt + 3 * N_EDGES;

    // ---- CSR build ----
    cudaMemsetAsync(p_cnt, 0, 4 * N_EDGES * sizeof(int));
    hist_kernel<<<(nnz + 255) / 256, 256>>>(node_idx, edge_idx, p_ncnt, p_ecnt, nnz);
    scan_kernel<<<2, 1024>>>(p_ecnt, p_eoff, p_ncnt, p_noff, p_binv, p_dinv, N_EDGES);
    fill_kernel<<<(nnz + 255) / 256, 256>>>(node_idx, edge_idx, p_eoff, p_noff,
                                            p_ecur, p_ncur, p_eadj, p_nadj, nnz);

    int agg_blocks = (N_EDGES * 32 + 255) / 256;
    dim3 ggrid((N_NODES + 127) / 128, 1);

    // ---- layer 1: h0 = x @ W1 ---- (M=50000, N=128, K=256)
    {
        dim3 grid((N_NODES + 127) / 128, HID_C / 64);
        tf32_gemm<<<grid, 256>>>(x, W1, p_h0, N_NODES, HID_C, IN_C, nullptr);
    }
    agg_kernel<4, false, false><<<agg_blocks, 256>>>(p_h0, p_eadj, p_eoff, nullptr,
                                                     p_m, nullptr, nullptr, N_EDGES);
    agg_kernel<4, true, true><<<agg_blocks, 256>>>(p_m, p_nadj, p_noff, p_binv,
                                                   f1, p_dinv, b1, N_NODES);

    // ---- layer 2: h1 = f1 @ W2 ---- (M=50000, N=64, K=128)
    tf32_gemm<<<ggrid, 256>>>(f1, W2, p_h1, N_NODES, OUT_C, HID_C, nullptr);
    agg_kernel<2, false, false><<<agg_blocks, 256>>>(p_h1, p_eadj, p_eoff, nullptr,
                                                     p_m, nullptr, nullptr, N_EDGES);
    agg_kernel<2, true, true><<<agg_blocks, 256>>>(p_m, p_nadj, p_noff, p_binv,
                                                   f2, p_dinv, b2, N_NODES);

    // ---- projection: z = f2 @ Wp + bp ---- (M=50000, N=64, K=64)
    tf32_gemm<<<ggrid, 256>>>(f2, Wp, z, N_NODES, OUT_C, OUT_C, bp);
}

// round 12
// speedup vs baseline: 1.8043x; 1.1268x over previous
#include <cuda_runtime.h>
#include <stdint.h>

#define N_NODES 50000
#define N_EDGES 50000
#define IN_C 256
#define HID_C 128
#define OUT_C 64
#define MAX_NNZ 800000

// ---------------- scratch (no allocations allowed) ----------------
__device__ float g_h0[(size_t)N_NODES * HID_C];   // x @ W1
__device__ float g_m [(size_t)N_EDGES * HID_C];   // edge aggregation buffer (reused at C=64)
__device__ float g_h1[(size_t)N_NODES * OUT_C];   // f1 @ W2
__device__ float g_dinv[N_NODES];
__device__ float g_binv[N_EDGES];

__device__ int g_cnt[4 * N_EDGES];   // [ecnt | ncnt | ecur | ncur]
__device__ int g_eoff[N_EDGES + 1];
__device__ int g_noff[N_NODES + 1];
__device__ int g_eadj[MAX_NNZ];
__device__ int g_nadj[MAX_NNZ];

// ---------------- histogram ----------------
__global__ void hist_kernel(const int* __restrict__ node_idx,
                            const int* __restrict__ edge_idx,
                            int* __restrict__ ncnt, int* __restrict__ ecnt, int nnz) {
    int t = blockIdx.x * blockDim.x + threadIdx.x;
    if (t < nnz) {
        atomicAdd(&ncnt[node_idx[t]], 1);
        atomicAdd(&ecnt[edge_idx[t]], 1);
    }
}

// ---------------- exclusive scan + fused 1/count ----------------
__global__ void scan_kernel(const int* __restrict__ cntE, int* __restrict__ offE,
                            const int* __restrict__ cntN, int* __restrict__ offN,
                            float* __restrict__ binv, float* __restrict__ dinv, int n) {
    const int* cnt = (blockIdx.x == 0) ? cntE : cntN;
    int* off       = (blockIdx.x == 0) ? offE : offN;
    float* inv     = (blockIdx.x == 0) ? binv : dinv;
    __shared__ int sh[1024];
    int tid = threadIdx.x;
    int chunk = (n + 1023) / 1024;
    int start = tid * chunk;
    int end = min(start + chunk, n);
    int s = 0;
    for (int i = start; i < end; i++) {
        int c = cnt[i];
        s += c;
        inv[i] = (c > 0) ? (1.0f / (float)c) : 0.0f;
    }
    sh[tid] = s;
    __syncthreads();
    for (int d = 1; d < 1024; d <<= 1) {
        int v = (tid >= d) ? sh[tid - d] : 0;
        __syncthreads();
        sh[tid] += v;
        __syncthreads();
    }
    int run = (tid == 0) ? 0 : sh[tid - 1];
    for (int i = start; i < end; i++) {
        off[i] = run;
        run += cnt[i];
    }
    if (tid == 1023) off[n] = sh[1023];
}

// ---------------- CSR fill ----------------
__global__ void fill_kernel(const int* __restrict__ node_idx, const int* __restrict__ edge_idx,
                            const int* __restrict__ eoff, const int* __restrict__ noff,
                            int* __restrict__ ecur, int* __restrict__ ncur,
                            int* __restrict__ eadj, int* __restrict__ nadj, int nnz) {
    int t = blockIdx.x * blockDim.x + threadIdx.x;
    if (t < nnz) {
        int nd = node_idx[t];
        int eg = edge_idx[t];
        int p = atomicAdd(&ecur[eg], 1);
        eadj[eoff[eg] + p] = nd;
        int q = atomicAdd(&ncur[nd], 1);
        nadj[noff[nd] + q] = eg;
    }
}

// ---------------- warp-per-row gather-reduce, 4x unrolled for MLP ----------------
template <int VEC, bool SRC_SCALE, bool FINAL>
__global__ void agg_kernel(const float* __restrict__ src, const int* __restrict__ adj,
                           const int* __restrict__ off, const float* __restrict__ sscale,
                           float* __restrict__ out, const float* __restrict__ rscale,
                           const float* __restrict__ bias, int rows) {
    int warp = (blockIdx.x * blockDim.x + threadIdx.x) >> 5;
    int lane = threadIdx.x & 31;
    if (warp >= rows) return;
    const int C = 32 * VEC;
    int s0 = off[warp];
    int s1 = off[warp + 1];
    int lo = lane * VEC;

    float acc[VEC];
#pragma unroll
    for (int k = 0; k < VEC; k++) acc[k] = 0.0f;

    int j = s0;
    for (; j + 4 <= s1; j += 4) {
        int nb0 = adj[j + 0];
        int nb1 = adj[j + 1];
        int nb2 = adj[j + 2];
        int nb3 = adj[j + 3];
        float c0 = SRC_SCALE ? sscale[nb0] : 1.0f;
        float c1 = SRC_SCALE ? sscale[nb1] : 1.0f;
        float c2 = SRC_SCALE ? sscale[nb2] : 1.0f;
        float c3 = SRC_SCALE ? sscale[nb3] : 1.0f;
        if (VEC == 4) {
            float4 v0 = *reinterpret_cast<const float4*>(src + (size_t)nb0 * C + lo);
            float4 v1 = *reinterpret_cast<const float4*>(src + (size_t)nb1 * C + lo);
            float4 v2 = *reinterpret_cast<const float4*>(src + (size_t)nb2 * C + lo);
            float4 v3 = *reinterpret_cast<const float4*>(src + (size_t)nb3 * C + lo);
            acc[0] += v0.x * c0 + v1.x * c1 + v2.x * c2 + v3.x * c3;
            acc[1] += v0.y * c0 + v1.y * c1 + v2.y * c2 + v3.y * c3;
            acc[2] += v0.z * c0 + v1.z * c1 + v2.z * c2 + v3.z * c3;
            acc[3] += v0.w * c0 + v1.w * c1 + v2.w * c2 + v3.w * c3;
        } else {
            float2 v0 = *reinterpret_cast<const float2*>(src + (size_t)nb0 * C + lo);
            float2 v1 = *reinterpret_cast<const float2*>(src + (size_t)nb1 * C + lo);
            float2 v2 = *reinterpret_cast<const float2*>(src + (size_t)nb2 * C + lo);
            float2 v3 = *reinterpret_cast<const float2*>(src + (size_t)nb3 * C + lo);
            acc[0] += v0.x * c0 + v1.x * c1 + v2.x * c2 + v3.x * c3;
            acc[1] += v0.y * c0 + v1.y * c1 + v2.y * c2 + v3.y * c3;
        }
    }
    for (; j < s1; j++) {
        int nb = adj[j];
        float sc = SRC_SCALE ? sscale[nb] : 1.0f;
        if (VEC == 4) {
            float4 v = *reinterpret_cast<const float4*>(src + (size_t)nb * C + lo);
            acc[0] += v.x * sc; acc[1] += v.y * sc;
            acc[2] += v.z * sc; acc[3] += v.w * sc;
        } else {
            float2 v = *reinterpret_cast<const float2*>(src + (size_t)nb * C + lo);
            acc[0] += v.x * sc; acc[1] += v.y * sc;
        }
    }

    float* q = out + (size_t)warp * C + lo;
    if (FINAL) {
        float rs = rscale[warp];
#pragma unroll
        for (int k = 0; k < VEC; k++)
            acc[k] = fmaxf(acc[k] * rs + bias[lo + k], 0.0f);
    }
    if (VEC == 4) {
        *reinterpret_cast<float4*>(q) = make_float4(acc[0], acc[1], acc[2], acc[3]);
    } else {
        *reinterpret_cast<float2*>(q) = make_float2(acc[0], acc[1]);
    }
}

// ---------------- 2xTF32 tensor-core GEMM (A split hi+lo, B single tf32) ----------------
__device__ __forceinline__ uint32_t f2tf32(float x) {
    uint32_t r;
    asm("cvt.rna.tf32.f32 %0, %1;" : "=r"(r) : "f"(x));
    return r;
}

__device__ __forceinline__ void mma_tf32(float* c, const uint32_t* a, const uint32_t* b) {
    asm("mma.sync.aligned.m16n8k8.row.col.f32.tf32.tf32.f32 "
        "{%0,%1,%2,%3}, {%4,%5,%6,%7}, {%8,%9}, {%0,%1,%2,%3};"
        : "+f"(c[0]), "+f"(c[1]), "+f"(c[2]), "+f"(c[3])
        : "r"(a[0]), "r"(a[1]), "r"(a[2]), "r"(a[3]), "r"(b[0]), "r"(b[1]));
}

// C[M,N] = A[M,K] @ B[K,N] (+bias). BM=128, BN=64, BK=32, 256 threads (8 warps, 4x2).
// A smem is row-major [m][k] stride 36: conflict-free STS.128 stores AND
// conflict-free fragment loads (bank = gid*4 + tg). All tf32 cvt at load time.
// Requires: N multiple of 64, K multiple of 32.
__global__ void __launch_bounds__(256)
tf32_gemm(const float* __restrict__ A, const float* __restrict__ B,
          float* __restrict__ C, int M, int N, int K,
          const float* __restrict__ bias) {
    const int BM = 128, BN = 64, BK = 32;
    const int AS = BK + 4;   // 36 words: stride*4 ≡ 16 mod 32? 36 mod 32 = 4 -> bank = m*4 + k
    __shared__ uint32_t Ahi[BM][AS];
    __shared__ uint32_t Alo[BM][AS];
    __shared__ uint32_t Bs [BK][BN + 8];   // stride 72

    int tid = threadIdx.x;
    int wid = tid >> 5;
    int lane = tid & 31;
    int gid = lane >> 2;       // 0..7
    int tg = lane & 3;         // 0..3
    int warp_m = wid >> 1;     // 0..3
    int warp_n = wid & 1;      // 0..1
    int mb = warp_m * 32;
    int nb = warp_n * 32;

    int rowBase = blockIdx.x * BM;
    int colBase = blockIdx.y * BN;

    float acc[2][4][4];
#pragma unroll
    for (int t = 0; t < 2; t++)
#pragma unroll
        for (int u = 0; u < 4; u++)
#pragma unroll
            for (int k = 0; k < 4; k++) acc[t][u][k] = 0.0f;

    for (int k0 = 0; k0 < K; k0 += BK) {
        // A tile: BM x BK row-major. 4096 elems, 4 float4/thread, STS.128 conflict-free.
#pragma unroll
        for (int it = 0; it < 4; it++) {
            int idx = tid * 4 + it * 1024;
            int r = idx / BK;
            int c = idx % BK;
            int gr = rowBase + r;
            float4 v = make_float4(0.f, 0.f, 0.f, 0.f);
            if (gr < M)
                v = *reinterpret_cast<const float4*>(A + (size_t)gr * K + k0 + c);
            uint4 hi, lo;
            hi.x = f2tf32(v.x); lo.x = f2tf32(v.x - __uint_as_float(hi.x));
            hi.y = f2tf32(v.y); lo.y = f2tf32(v.y - __uint_as_float(hi.y));
            hi.z = f2tf32(v.z); lo.z = f2tf32(v.z - __uint_as_float(hi.z));
            hi.w = f2tf32(v.w); lo.w = f2tf32(v.w - __uint_as_float(hi.w));
            *reinterpret_cast<uint4*>(&Ahi[r][c]) = hi;
            *reinterpret_cast<uint4*>(&Alo[r][c]) = lo;
        }
        // B tile: BK x BN. 2048 elems, 2 float4/thread.
#pragma unroll
        for (int it = 0; it < 2; it++) {
            int idx = tid * 4 + it * 1024;
            int r = idx / BN;
            int c = idx % BN;
            float4 v = *reinterpret_cast<const float4*>(B + (size_t)(k0 + r) * N + colBase + c);
            Bs[r][c + 0] = f2tf32(v.x);
            Bs[r][c + 1] = f2tf32(v.y);
            Bs[r][c + 2] = f2tf32(v.z);
            Bs[r][c + 3] = f2tf32(v.w);
        }
        __syncthreads();

#pragma unroll
        for (int ks = 0; ks < 4; ks++) {
            int k = ks * 8;
            uint32_t ahi[2][4], alo[2][4];
#pragma unroll
            for (int t = 0; t < 2; t++) {
                int m = mb + t * 16 + gid;
                ahi[t][0] = Ahi[m][k + tg];
                ahi[t][1] = Ahi[m + 8][k + tg];
                ahi[t][2] = Ahi[m][k + tg + 4];
                ahi[t][3] = Ahi[m + 8][k + tg + 4];
                alo[t][0] = Alo[m][k + tg];
                alo[t][1] = Alo[m + 8][k + tg];
                alo[t][2] = Alo[m][k + tg + 4];
                alo[t][3] = Alo[m + 8][k + tg + 4];
            }
            uint32_t bf[4][2];
#pragma unroll
            for (int u = 0; u < 4; u++) {
                int n = nb + u * 8 + gid;
                bf[u][0] = Bs[k + tg][n];
                bf[u][1] = Bs[k + tg + 4][n];
            }
#pragma unroll
            for (int t = 0; t < 2; t++)
#pragma unroll
                for (int u = 0; u < 4; u++) {
                    mma_tf32(acc[t][u], ahi[t], bf[u]);
                    mma_tf32(acc[t][u], alo[t], bf[u]);
                }
        }
        __syncthreads();
    }

#pragma unroll
    for (int t = 0; t < 2; t++) {
#pragma unroll
        for (int u = 0; u < 4; u++) {
            int row = rowBase + mb + t * 16 + gid;
            int col = colBase + nb + u * 8 + tg * 2;
            float b0 = 0.f, b1 = 0.f;
            if (bias) { b0 = bias[col]; b1 = bias[col + 1]; }
            if (row < M) {
                float2 v = make_float2(acc[t][u][0] + b0, acc[t][u][1] + b1);
                *reinterpret_cast<float2*>(C + (size_t)row * N + col) = v;
            }
            if (row + 8 < M) {
                float2 v = make_float2(acc[t][u][2] + b0, acc[t][u][3] + b1);
                *reinterpret_cast<float2*>(C + (size_t)(row + 8) * N + col) = v;
            }
        }
    }
}

// ---------------- launch ----------------
extern "C" void kernel_launch(void* const* d_in, const int* in_sizes, int n_in,
                              void* d_out, int out_size) {
    const float* x    = (const float*)d_in[0];
    const int*   hidx = (const int*)d_in[1];   // int32 on device (JAX x64 disabled)
    const float* W1   = (const float*)d_in[2];
    const float* b1   = (const float*)d_in[3];
    const float* W2   = (const float*)d_in[4];
    const float* b2   = (const float*)d_in[5];
    const float* Wp   = (const float*)d_in[6];
    const float* bp   = (const float*)d_in[7];

    int nnz = in_sizes[1] / 2;
    const int* node_idx = hidx;
    const int* edge_idx = hidx + nnz;

    // output layout: (z [N,64], features_1 [N,128], features_2 [N,64])
    float* z  = (float*)d_out;
    float* f1 = z  + (size_t)N_NODES * OUT_C;
    float* f2 = f1 + (size_t)N_NODES * HID_C;

    float *p_h0, *p_m, *p_h1, *p_dinv, *p_binv;
    int *p_cnt, *p_eoff, *p_noff, *p_eadj, *p_nadj;
    cudaGetSymbolAddress((void**)&p_h0,   g_h0);
    cudaGetSymbolAddress((void**)&p_m,    g_m);
    cudaGetSymbolAddress((void**)&p_h1,   g_h1);
    cudaGetSymbolAddress((void**)&p_dinv, g_dinv);
    cudaGetSymbolAddress((void**)&p_binv, g_binv);
    cudaGetSymbolAddress((void**)&p_cnt,  g_cnt);
    cudaGetSymbolAddress((void**)&p_eoff, g_eoff);
    cudaGetSymbolAddress((void**)&p_noff, g_noff);
    cudaGetSymbolAddress((void**)&p_eadj, g_eadj);
    cudaGetSymbolAddress((void**)&p_nadj, g_nadj);

    int* p_ecnt = p_cnt;
    int* p_ncnt = p_cnt + N_EDGES;
    int* p_ecur = p_cnt + 2 * N_EDGES;
    int* p_ncur = p_cnt + 3 * N_EDGES;

    // ---- CSR build ----
    cudaMemsetAsync(p_cnt, 0, 4 * N_EDGES * sizeof(int));
    hist_kernel<<<(nnz + 255) / 256, 256>>>(node_idx, edge_idx, p_ncnt, p_ecnt, nnz);
    scan_kernel<<<2, 1024>>>(p_ecnt, p_eoff, p_ncnt, p_noff, p_binv, p_dinv, N_EDGES);
    fill_kernel<<<(nnz + 255) / 256, 256>>>(node_idx, edge_idx, p_eoff, p_noff,
                                            p_ecur, p_ncur, p_eadj, p_nadj, nnz);

    int agg_blocks = (N_EDGES * 32 + 255) / 256;
    dim3 ggrid((N_NODES + 127) / 128, 1);

    // ---- layer 1: h0 = x @ W1 ---- (M=50000, N=128, K=256)
    {
        dim3 grid((N_NODES + 127) / 128, HID_C / 64);
        tf32_gemm<<<grid, 256>>>(x, W1, p_h0, N_NODES, HID_C, IN_C, nullptr);
    }
    agg_kernel<4, false, false><<<agg_blocks, 256>>>(p_h0, p_eadj, p_eoff, nullptr,
                                                     p_m, nullptr, nullptr, N_EDGES);
    agg_kernel<4, true, true><<<agg_blocks, 256>>>(p_m, p_nadj, p_noff, p_binv,
                                                   f1, p_dinv, b1, N_NODES);

    // ---- layer 2: h1 = f1 @ W2 ---- (M=50000, N=64, K=128)
    tf32_gemm<<<ggrid, 256>>>(f1, W2, p_h1, N_NODES, OUT_C, HID_C, nullptr);
    agg_kernel<2, false, false><<<agg_blocks, 256>>>(p_h1, p_eadj, p_eoff, nullptr,
                                                     p_m, nullptr, nullptr, N_EDGES);
    agg_kernel<2, true, true><<<agg_blocks, 256>>>(p_m, p_nadj, p_noff, p_binv,
                                                   f2, p_dinv, b2, N_NODES);

    // ---- projection: z = f2 @ Wp + bp ---- (M=50000, N=64, K=64)
    tf32_gemm<<<ggrid, 256>>>(f2, Wp, z, N_NODES, OUT_C, OUT_C, bp);
}

// round 13
// speedup vs baseline: 1.8769x; 1.0402x over previous
#include <cuda_runtime.h>
#include <cuda_fp16.h>
#include <stdint.h>

#define N_NODES 50000
#define N_EDGES 50000
#define IN_C 256
#define HID_C 128
#define OUT_C 64
#define MAX_NNZ 800000

// ---------------- scratch (no allocations allowed) ----------------
__device__ __half g_h0h[(size_t)N_NODES * HID_C];  // x @ W1 (fp16)
__device__ __half g_h1h[(size_t)N_NODES * OUT_C];  // f1 @ W2 (fp16)
__device__ __half g_mh [(size_t)N_EDGES * HID_C];  // edge buffer (fp16, reused at C=64)
__device__ float g_dinv[N_NODES];
__device__ float g_binv[N_EDGES];

__device__ int g_cnt[4 * N_EDGES];   // [ecnt | ncnt | ecur | ncur]
__device__ int g_eoff[N_EDGES + 1];
__device__ int g_noff[N_NODES + 1];
__device__ int g_eadj[MAX_NNZ];
__device__ int g_nadj[MAX_NNZ];

// ---------------- histogram ----------------
__global__ void hist_kernel(const int* __restrict__ node_idx,
                            const int* __restrict__ edge_idx,
                            int* __restrict__ ncnt, int* __restrict__ ecnt, int nnz) {
    int t = blockIdx.x * blockDim.x + threadIdx.x;
    if (t < nnz) {
        atomicAdd(&ncnt[node_idx[t]], 1);
        atomicAdd(&ecnt[edge_idx[t]], 1);
    }
}

// ---------------- exclusive scan + fused 1/count ----------------
__global__ void scan_kernel(const int* __restrict__ cntE, int* __restrict__ offE,
                            const int* __restrict__ cntN, int* __restrict__ offN,
                            float* __restrict__ binv, float* __restrict__ dinv, int n) {
    const int* cnt = (blockIdx.x == 0) ? cntE : cntN;
    int* off       = (blockIdx.x == 0) ? offE : offN;
    float* inv     = (blockIdx.x == 0) ? binv : dinv;
    __shared__ int sh[1024];
    int tid = threadIdx.x;
    int chunk = (n + 1023) / 1024;
    int start = tid * chunk;
    int end = min(start + chunk, n);
    int s = 0;
    for (int i = start; i < end; i++) {
        int c = cnt[i];
        s += c;
        inv[i] = (c > 0) ? (1.0f / (float)c) : 0.0f;
    }
    sh[tid] = s;
    __syncthreads();
    for (int d = 1; d < 1024; d <<= 1) {
        int v = (tid >= d) ? sh[tid - d] : 0;
        __syncthreads();
        sh[tid] += v;
        __syncthreads();
    }
    int run = (tid == 0) ? 0 : sh[tid - 1];
    for (int i = start; i < end; i++) {
        off[i] = run;
        run += cnt[i];
    }
    if (tid == 1023) off[n] = sh[1023];
}

// ---------------- CSR fill ----------------
__global__ void fill_kernel(const int* __restrict__ node_idx, const int* __restrict__ edge_idx,
                            const int* __restrict__ eoff, const int* __restrict__ noff,
                            int* __restrict__ ecur, int* __restrict__ ncur,
                            int* __restrict__ eadj, int* __restrict__ nadj, int nnz) {
    int t = blockIdx.x * blockDim.x + threadIdx.x;
    if (t < nnz) {
        int nd = node_idx[t];
        int eg = edge_idx[t];
        int p = atomicAdd(&ecur[eg], 1);
        eadj[eoff[eg] + p] = nd;
        int q = atomicAdd(&ncur[nd], 1);
        nadj[noff[nd] + q] = eg;
    }
}

// ---------------- pass1: fp16 gather -> fp32 accum -> fp16 out (edge rows) ----------------
// out[row] = sum over nb of src[nb];  C = 32*VEC channels (VEC halves per lane).
template <int VEC>
__global__ void agg_p1(const __half* __restrict__ src, const int* __restrict__ adj,
                       const int* __restrict__ off, __half* __restrict__ out, int rows) {
    int warp = (blockIdx.x * blockDim.x + threadIdx.x) >> 5;
    int lane = threadIdx.x & 31;
    if (warp >= rows) return;
    const int C = 32 * VEC;
    int s0 = off[warp];
    int s1 = off[warp + 1];
    int lo = lane * VEC;   // in halves

    float acc[VEC];
#pragma unroll
    for (int k = 0; k < VEC; k++) acc[k] = 0.0f;

    int j = s0;
    for (; j + 4 <= s1; j += 4) {
        int nb0 = adj[j + 0], nb1 = adj[j + 1], nb2 = adj[j + 2], nb3 = adj[j + 3];
        const __half2* p0 = reinterpret_cast<const __half2*>(src + (size_t)nb0 * C + lo);
        const __half2* p1 = reinterpret_cast<const __half2*>(src + (size_t)nb1 * C + lo);
        const __half2* p2 = reinterpret_cast<const __half2*>(src + (size_t)nb2 * C + lo);
        const __half2* p3 = reinterpret_cast<const __half2*>(src + (size_t)nb3 * C + lo);
#pragma unroll
        for (int h = 0; h < VEC / 2; h++) {
            float2 a = __half22float2(p0[h]);
            float2 b = __half22float2(p1[h]);
            float2 c = __half22float2(p2[h]);
            float2 d = __half22float2(p3[h]);
            acc[2 * h + 0] += a.x + b.x + c.x + d.x;
            acc[2 * h + 1] += a.y + b.y + c.y + d.y;
        }
    }
    for (; j < s1; j++) {
        int nb = adj[j];
        const __half2* p = reinterpret_cast<const __half2*>(src + (size_t)nb * C + lo);
#pragma unroll
        for (int h = 0; h < VEC / 2; h++) {
            float2 a = __half22float2(p[h]);
            acc[2 * h + 0] += a.x;
            acc[2 * h + 1] += a.y;
        }
    }

    __half2* q = reinterpret_cast<__half2*>(out + (size_t)warp * C + lo);
#pragma unroll
    for (int h = 0; h < VEC / 2; h++)
        q[h] = __floats2half2_rn(acc[2 * h + 0], acc[2 * h + 1]);
}

// ---------------- pass2: fp16 gather (scaled) -> fp32 final with dinv/bias/relu ----------------
template <int VEC>
__global__ void agg_p2(const __half* __restrict__ src, const int* __restrict__ adj,
                       const int* __restrict__ off, const float* __restrict__ sscale,
                       float* __restrict__ out, const float* __restrict__ rscale,
                       const float* __restrict__ bias, int rows) {
    int warp = (blockIdx.x * blockDim.x + threadIdx.x) >> 5;
    int lane = threadIdx.x & 31;
    if (warp >= rows) return;
    const int C = 32 * VEC;
    int s0 = off[warp];
    int s1 = off[warp + 1];
    int lo = lane * VEC;

    float acc[VEC];
#pragma unroll
    for (int k = 0; k < VEC; k++) acc[k] = 0.0f;

    int j = s0;
    for (; j + 4 <= s1; j += 4) {
        int nb0 = adj[j + 0], nb1 = adj[j + 1], nb2 = adj[j + 2], nb3 = adj[j + 3];
        float c0 = sscale[nb0], c1 = sscale[nb1], c2 = sscale[nb2], c3 = sscale[nb3];
        const __half2* p0 = reinterpret_cast<const __half2*>(src + (size_t)nb0 * C + lo);
        const __half2* p1 = reinterpret_cast<const __half2*>(src + (size_t)nb1 * C + lo);
        const __half2* p2 = reinterpret_cast<const __half2*>(src + (size_t)nb2 * C + lo);
        const __half2* p3 = reinterpret_cast<const __half2*>(src + (size_t)nb3 * C + lo);
#pragma unroll
        for (int h = 0; h < VEC / 2; h++) {
            float2 a = __half22float2(p0[h]);
            float2 b = __half22float2(p1[h]);
            float2 c = __half22float2(p2[h]);
            float2 d = __half22float2(p3[h]);
            acc[2 * h + 0] += a.x * c0 + b.x * c1 + c.x * c2 + d.x * c3;
            acc[2 * h + 1] += a.y * c0 + b.y * c1 + c.y * c2 + d.y * c3;
        }
    }
    for (; j < s1; j++) {
        int nb = adj[j];
        float sc = sscale[nb];
        const __half2* p = reinterpret_cast<const __half2*>(src + (size_t)nb * C + lo);
#pragma unroll
        for (int h = 0; h < VEC / 2; h++) {
            float2 a = __half22float2(p[h]);
            acc[2 * h + 0] += a.x * sc;
            acc[2 * h + 1] += a.y * sc;
        }
    }

    float rs = rscale[warp];
#pragma unroll
    for (int k = 0; k < VEC; k++)
        acc[k] = fmaxf(acc[k] * rs + bias[lo + k], 0.0f);

    float* q = out + (size_t)warp * C + lo;
    if (VEC == 4) {
        *reinterpret_cast<float4*>(q) = make_float4(acc[0], acc[1], acc[2], acc[3]);
    } else {
        *reinterpret_cast<float2*>(q) = make_float2(acc[0], acc[1]);
    }
}

// ---------------- 2xTF32 tensor-core GEMM (A split hi+lo, B single tf32) ----------------
__device__ __forceinline__ uint32_t f2tf32(float x) {
    uint32_t r;
    asm("cvt.rna.tf32.f32 %0, %1;" : "=r"(r) : "f"(x));
    return r;
}

__device__ __forceinline__ void mma_tf32(float* c, const uint32_t* a, const uint32_t* b) {
    asm("mma.sync.aligned.m16n8k8.row.col.f32.tf32.tf32.f32 "
        "{%0,%1,%2,%3}, {%4,%5,%6,%7}, {%8,%9}, {%0,%1,%2,%3};"
        : "+f"(c[0]), "+f"(c[1]), "+f"(c[2]), "+f"(c[3])
        : "r"(a[0]), "r"(a[1]), "r"(a[2]), "r"(a[3]), "r"(b[0]), "r"(b[1]));
}

// C[M,N] = A[M,K] @ B[K,N] (+bias fp32 path). BM=128, BN=64, BK=32, 256 threads.
// A smem row-major [m][k] stride 36 (conflict-free stores and frag loads).
// HALF_OUT: write fp16 (no bias). Requires N multiple of 64, K multiple of 32.
template <bool HALF_OUT>
__global__ void __launch_bounds__(256)
tf32_gemm(const float* __restrict__ A, const float* __restrict__ B,
          void* __restrict__ Cv, int M, int N, int K,
          const float* __restrict__ bias) {
    const int BM = 128, BN = 64, BK = 32;
    const int AS = BK + 4;   // stride 36 words
    __shared__ uint32_t Ahi[BM][AS];
    __shared__ uint32_t Alo[BM][AS];
    __shared__ uint32_t Bs [BK][BN + 8];

    int tid = threadIdx.x;
    int wid = tid >> 5;
    int lane = tid & 31;
    int gid = lane >> 2;
    int tg = lane & 3;
    int warp_m = wid >> 1;
    int warp_n = wid & 1;
    int mb = warp_m * 32;
    int nb = warp_n * 32;

    int rowBase = blockIdx.x * BM;
    int colBase = blockIdx.y * BN;

    float acc[2][4][4];
#pragma unroll
    for (int t = 0; t < 2; t++)
#pragma unroll
        for (int u = 0; u < 4; u++)
#pragma unroll
            for (int k = 0; k < 4; k++) acc[t][u][k] = 0.0f;

    for (int k0 = 0; k0 < K; k0 += BK) {
#pragma unroll
        for (int it = 0; it < 4; it++) {
            int idx = tid * 4 + it * 1024;
            int r = idx / BK;
            int c = idx % BK;
            int gr = rowBase + r;
            float4 v = make_float4(0.f, 0.f, 0.f, 0.f);
            if (gr < M)
                v = *reinterpret_cast<const float4*>(A + (size_t)gr * K + k0 + c);
            uint4 hi, lo;
            hi.x = f2tf32(v.x); lo.x = f2tf32(v.x - __uint_as_float(hi.x));
            hi.y = f2tf32(v.y); lo.y = f2tf32(v.y - __uint_as_float(hi.y));
            hi.z = f2tf32(v.z); lo.z = f2tf32(v.z - __uint_as_float(hi.z));
            hi.w = f2tf32(v.w); lo.w = f2tf32(v.w - __uint_as_float(hi.w));
            *reinterpret_cast<uint4*>(&Ahi[r][c]) = hi;
            *reinterpret_cast<uint4*>(&Alo[r][c]) = lo;
        }
#pragma unroll
        for (int it = 0; it < 2; it++) {
            int idx = tid * 4 + it * 1024;
            int r = idx / BN;
            int c = idx % BN;
            float4 v = *reinterpret_cast<const float4*>(B + (size_t)(k0 + r) * N + colBase + c);
            Bs[r][c + 0] = f2tf32(v.x);
            Bs[r][c + 1] = f2tf32(v.y);
            Bs[r][c + 2] = f2tf32(v.z);
            Bs[r][c + 3] = f2tf32(v.w);
        }
        __syncthreads();

#pragma unroll
        for (int ks = 0; ks < 4; ks++) {
            int k = ks * 8;
            uint32_t ahi[2][4], alo[2][4];
#pragma unroll
            for (int t = 0; t < 2; t++) {
                int m = mb + t * 16 + gid;
                ahi[t][0] = Ahi[m][k + tg];
                ahi[t][1] = Ahi[m + 8][k + tg];
                ahi[t][2] = Ahi[m][k + tg + 4];
                ahi[t][3] = Ahi[m + 8][k + tg + 4];
                alo[t][0] = Alo[m][k + tg];
                alo[t][1] = Alo[m + 8][k + tg];
                alo[t][2] = Alo[m][k + tg + 4];
                alo[t][3] = Alo[m + 8][k + tg + 4];
            }
            uint32_t bf[4][2];
#pragma unroll
            for (int u = 0; u < 4; u++) {
                int n = nb + u * 8 + gid;
                bf[u][0] = Bs[k + tg][n];
                bf[u][1] = Bs[k + tg + 4][n];
            }
#pragma unroll
            for (int t = 0; t < 2; t++)
#pragma unroll
                for (int u = 0; u < 4; u++) {
                    mma_tf32(acc[t][u], ahi[t], bf[u]);
                    mma_tf32(acc[t][u], alo[t], bf[u]);
                }
        }
        __syncthreads();
    }

#pragma unroll
    for (int t = 0; t < 2; t++) {
#pragma unroll
        for (int u = 0; u < 4; u++) {
            int row = rowBase + mb + t * 16 + gid;
            int col = colBase + nb + u * 8 + tg * 2;
            if (HALF_OUT) {
                __half* C = (__half*)Cv;
                if (row < M)
                    *reinterpret_cast<__half2*>(C + (size_t)row * N + col) =
                        __floats2half2_rn(acc[t][u][0], acc[t][u][1]);
                if (row + 8 < M)
                    *reinterpret_cast<__half2*>(C + (size_t)(row + 8) * N + col) =
                        __floats2half2_rn(acc[t][u][2], acc[t][u][3]);
            } else {
                float* C = (float*)Cv;
                float b0 = 0.f, b1 = 0.f;
                if (bias) { b0 = bias[col]; b1 = bias[col + 1]; }
                if (row < M) {
                    float2 v = make_float2(acc[t][u][0] + b0, acc[t][u][1] + b1);
                    *reinterpret_cast<float2*>(C + (size_t)row * N + col) = v;
                }
                if (row + 8 < M) {
                    float2 v = make_float2(acc[t][u][2] + b0, acc[t][u][3] + b1);
                    *reinterpret_cast<float2*>(C + (size_t)(row + 8) * N + col) = v;
                }
            }
        }
    }
}

// ---------------- launch ----------------
extern "C" void kernel_launch(void* const* d_in, const int* in_sizes, int n_in,
                              void* d_out, int out_size) {
    const float* x    = (const float*)d_in[0];
    const int*   hidx = (const int*)d_in[1];   // int32 on device (JAX x64 disabled)
    const float* W1   = (const float*)d_in[2];
    const float* b1   = (const float*)d_in[3];
    const float* W2   = (const float*)d_in[4];
    const float* b2   = (const float*)d_in[5];
    const float* Wp   = (const float*)d_in[6];
    const float* bp   = (const float*)d_in[7];

    int nnz = in_sizes[1] / 2;
    const int* node_idx = hidx;
    const int* edge_idx = hidx + nnz;

    // output layout: (z [N,64], features_1 [N,128], features_2 [N,64])
    float* z  = (float*)d_out;
    float* f1 = z  + (size_t)N_NODES * OUT_C;
    float* f2 = f1 + (size_t)N_NODES * HID_C;

    __half *p_h0h, *p_h1h, *p_mh;
    float *p_dinv, *p_binv;
    int *p_cnt, *p_eoff, *p_noff, *p_eadj, *p_nadj;
    cudaGetSymbolAddress((void**)&p_h0h,  g_h0h);
    cudaGetSymbolAddress((void**)&p_h1h,  g_h1h);
    cudaGetSymbolAddress((void**)&p_mh,   g_mh);
    cudaGetSymbolAddress((void**)&p_dinv, g_dinv);
    cudaGetSymbolAddress((void**)&p_binv, g_binv);
    cudaGetSymbolAddress((void**)&p_cnt,  g_cnt);
    cudaGetSymbolAddress((void**)&p_eoff, g_eoff);
    cudaGetSymbolAddress((void**)&p_noff, g_noff);
    cudaGetSymbolAddress((void**)&p_eadj, g_eadj);
    cudaGetSymbolAddress((void**)&p_nadj, g_nadj);

    int* p_ecnt = p_cnt;
    int* p_ncnt = p_cnt + N_EDGES;
    int* p_ecur = p_cnt + 2 * N_EDGES;
    int* p_ncur = p_cnt + 3 * N_EDGES;

    // ---- CSR build ----
    cudaMemsetAsync(p_cnt, 0, 4 * N_EDGES * sizeof(int));
    hist_kernel<<<(nnz + 255) / 256, 256>>>(node_idx, edge_idx, p_ncnt, p_ecnt, nnz);
    scan_kernel<<<2, 1024>>>(p_ecnt, p_eoff, p_ncnt, p_noff, p_binv, p_dinv, N_EDGES);
    fill_kernel<<<(nnz + 255) / 256, 256>>>(node_idx, edge_idx, p_eoff, p_noff,
                                            p_ecur, p_ncur, p_eadj, p_nadj, nnz);

    int agg_blocks = (N_EDGES * 32 + 255) / 256;
    dim3 ggrid((N_NODES + 127) / 128, 1);

    // ---- layer 1: h0 = x @ W1 (fp16 out) ---- (M=50000, N=128, K=256)
    {
        dim3 grid((N_NODES + 127) / 128, HID_C / 64);
        tf32_gemm<true><<<grid, 256>>>(x, W1, p_h0h, N_NODES, HID_C, IN_C, nullptr);
    }
    agg_p1<4><<<agg_blocks, 256>>>(p_h0h, p_eadj, p_eoff, p_mh, N_EDGES);
    agg_p2<4><<<agg_blocks, 256>>>(p_mh, p_nadj, p_noff, p_binv, f1, p_dinv, b1, N_NODES);

    // ---- layer 2: h1 = f1 @ W2 (fp16 out) ---- (M=50000, N=64, K=128)
    tf32_gemm<true><<<ggrid, 256>>>(f1, W2, p_h1h, N_NODES, OUT_C, HID_C, nullptr);
    agg_p1<2><<<agg_blocks, 256>>>(p_h1h, p_eadj, p_eoff, p_mh, N_EDGES);
    agg_p2<2><<<agg_blocks, 256>>>(p_mh, p_nadj, p_noff, p_binv, f2, p_dinv, b2, N_NODES);

    // ---- projection: z = f2 @ Wp + bp (fp32 out) ---- (M=50000, N=64, K=64)
    tf32_gemm<false><<<ggrid, 256>>>(f2, Wp, z, N_NODES, OUT_C, OUT_C, bp);
}